// round 13
// baseline (speedup 1.0000x reference)
#include <cuda_runtime.h>
#include <cuda_fp16.h>
#include <math.h>
#include <stdint.h>

#define NN 100000
#define NE 1600000
#define NFEAT 256
#define NHID1 128
#define NCLASS 64
#define NGRAPH 64

// ---------------- scratch (device globals; no allocation) ----------------
__device__ int    d_idx64;
__device__ float  d_deg[NN];      // zeroed by gather2 tail each call
__device__ float  d_dinv[NN];
__device__ int    d_counts[NN];   // zeroed by gather2 tail each call
__device__ int    d_rowstart[NN]; // after csr_fill: row END (start = end - cnt)
__device__ int    d_blockSums[128];
__device__ int2   d_csr[NE];      // (src, val-bits) packed
__device__ __half d_xw1[NN * NHID1];
__device__ __half d_h1[NN * NHID1];
__device__ __half d_xw2[NN * NCLASS];
__device__ float  d_pooled[NGRAPH * NCLASS];

__device__ __forceinline__ int load_idx(const int* __restrict__ p, long long i) {
    return d_idx64 ? p[2 * i] : p[i];
}

// ---------------- dtype detect ----------------
__global__ void detect_kernel(const int* __restrict__ ei) {
    if (threadIdx.x == 0) {
        int allzero = 1;
        for (int k = 0; k < 128; k++)
            if (ei[2 * k + 1] != 0) { allzero = 0; break; }
        d_idx64 = allzero;
    }
}

// ---------------- degree accumulation (4 edges / thread) ----------------
__global__ void edge_deg_kernel(const int* __restrict__ ei,
                                const float* __restrict__ ew) {
    int e = (blockIdx.x * blockDim.x + threadIdx.x) * 4;
    if (e >= NE) return;
    int c[4];
    if (d_idx64) {
        const int4* p = reinterpret_cast<const int4*>(ei + 2LL * (NE + e));
        int4 a = p[0], b = p[1];
        c[0] = a.x; c[1] = a.z; c[2] = b.x; c[3] = b.z;
    } else {
        int4 a = *reinterpret_cast<const int4*>(ei + NE + e);
        c[0] = a.x; c[1] = a.y; c[2] = a.z; c[3] = a.w;
    }
    float4 w = *reinterpret_cast<const float4*>(ew + e);
    float wv[4] = {w.x, w.y, w.z, w.w};
#pragma unroll
    for (int j = 0; j < 4; j++) {
        atomicAdd(&d_deg[c[j]], wv[j]);
        atomicAdd(&d_counts[c[j]], 1);
    }
}

// ---------------- block scan of counts + dinv (self-loop +1 here) ----------
__global__ void scan_dinv_kernel() {
    __shared__ int s[1024];
    int i = blockIdx.x * 1024 + threadIdx.x;
    int v = (i < NN) ? d_counts[i] : 0;
    s[threadIdx.x] = v;
    if (i < NN) d_dinv[i] = rsqrtf(d_deg[i] + 1.0f);   // +1 = self-loop weight
    __syncthreads();
    for (int off = 1; off < 1024; off <<= 1) {
        int t = (threadIdx.x >= off) ? s[threadIdx.x - off] : 0;
        __syncthreads();
        s[threadIdx.x] += t;
        __syncthreads();
    }
    if (i < NN) d_rowstart[i] = s[threadIdx.x] - v;
    if (threadIdx.x == 1023) d_blockSums[blockIdx.x] = s[1023];
}

// ---------------- per-block prefix + offsets + pool zeroing ----------------
__global__ void add_offsets_kernel(int nb) {
    __shared__ int total;
    if (threadIdx.x == 0) total = 0;
    __syncthreads();
    if (threadIdx.x < (unsigned)blockIdx.x && threadIdx.x < (unsigned)nb)
        atomicAdd(&total, d_blockSums[threadIdx.x]);
    __syncthreads();
    int i = blockIdx.x * 1024 + threadIdx.x;
    if (i < NN) d_rowstart[i] += total;
    if (i < NGRAPH * NCLASS) d_pooled[i] = 0.f;
}

// ---------------- CSR fill (4 edges / thread, bumps rowstart to end) -------
__global__ void csr_fill_kernel(const int* __restrict__ ei,
                                const float* __restrict__ ew) {
    int e = (blockIdx.x * blockDim.x + threadIdx.x) * 4;
    if (e >= NE) return;
    int r[4], c[4];
    if (d_idx64) {
        const int4* pr = reinterpret_cast<const int4*>(ei + 2LL * e);
        int4 a = pr[0], b = pr[1];
        r[0] = a.x; r[1] = a.z; r[2] = b.x; r[3] = b.z;
        const int4* pc = reinterpret_cast<const int4*>(ei + 2LL * (NE + e));
        int4 d = pc[0], f = pc[1];
        c[0] = d.x; c[1] = d.z; c[2] = f.x; c[3] = f.z;
    } else {
        int4 a = *reinterpret_cast<const int4*>(ei + e);
        r[0] = a.x; r[1] = a.y; r[2] = a.z; r[3] = a.w;
        int4 d = *reinterpret_cast<const int4*>(ei + NE + e);
        c[0] = d.x; c[1] = d.y; c[2] = d.z; c[3] = d.w;
    }
    float4 w = *reinterpret_cast<const float4*>(ew + e);
    float wv[4] = {w.x, w.y, w.z, w.w};
#pragma unroll
    for (int j = 0; j < 4; j++) {
        int pos = atomicAdd(&d_rowstart[c[j]], 1);
        d_csr[pos] = make_int2(r[j], __float_as_int(d_dinv[r[j]] * wv[j]));
    }
}

// ---------------- fp16 tensor-core GEMM, full-B-in-smem -------------------
__device__ __forceinline__ uint32_t packh2(float a, float b) {
    __half2 h = __floats2half2_rn(a, b);
    return *reinterpret_cast<uint32_t*>(&h);
}

__device__ __forceinline__ uint4 ldsm_x4(uint32_t addr) {
    uint4 r;
    asm volatile("ldmatrix.sync.aligned.m8n8.x4.shared.b16 {%0,%1,%2,%3}, [%4];"
                 : "=r"(r.x), "=r"(r.y), "=r"(r.z), "=r"(r.w) : "r"(addr));
    return r;
}

__device__ __forceinline__ uint4 ldsm_x4_trans(uint32_t addr) {
    uint4 r;
    asm volatile("ldmatrix.sync.aligned.m8n8.x4.trans.shared.b16 {%0,%1,%2,%3}, [%4];"
                 : "=r"(r.x), "=r"(r.y), "=r"(r.z), "=r"(r.w) : "r"(addr));
    return r;
}

__device__ __forceinline__ void mma_f16(float* c, uint4 a, uint32_t b0, uint32_t b1) {
    asm volatile(
        "mma.sync.aligned.m16n8k16.row.col.f32.f16.f16.f32 "
        "{%0,%1,%2,%3},{%4,%5,%6,%7},{%8,%9},{%0,%1,%2,%3};\n"
        : "+f"(c[0]), "+f"(c[1]), "+f"(c[2]), "+f"(c[3])
        : "r"(a.x), "r"(a.y), "r"(a.z), "r"(a.w), "r"(b0), "r"(b1));
}

// 256 threads = 8 warps (2M x 4N). BM=128, BK=32. A double-buffered,
// B (KTOT x BN) fully resident in smem (loaded once in prologue).
template <int BN, int KTOT, int AHALF>
__global__ void __launch_bounds__(256, 2)
hgemm_kernel(const void* __restrict__ Ap, const float* __restrict__ B,
             __half* __restrict__ C, int M) {
    const int BM = 128, BK = 32;
    const int PA = 40;
    const int PB = BN + 8;
    const int TN_AT = BN / 32;
    const int NPAIR = BN / 64;
    const int ABYTES = BM * PA * 2;
    const int NKT = KTOT / BK;

    extern __shared__ __half dsm[];
    __half* Ash = dsm;                      // 2 * BM * PA halfs
    __half* Bsh = dsm + 2 * BM * PA;        // KTOT * PB halfs

    const int tid = threadIdx.x;
    const int lane = tid & 31;
    const int warp = tid >> 5;
    const int wm = warp & 1;
    const int wn = warp >> 1;
    const int m0 = blockIdx.x * BM;

    const int l7 = lane & 7;
    const int l8 = (lane >> 3) & 1;
    const int l16 = lane >> 4;

    float acc[4][TN_AT][4];
#pragma unroll
    for (int i = 0; i < 4; i++)
#pragma unroll
        for (int j = 0; j < TN_AT; j++)
#pragma unroll
            for (int q = 0; q < 4; q++) acc[i][j][q] = 0.f;

    uint4 aU[2];
    uint2 aH[4];

    auto loadA = [&](int kt) {
        if (AHALF) {
            const __half* A = (const __half*)Ap;
#pragma unroll
            for (int i = 0; i < 2; i++) {
                int idx = tid + i * 256;
                int r = idx >> 2;
                int c = (idx & 3) * 8;
                if (m0 + r < M)
                    aU[i] = *reinterpret_cast<const uint4*>(
                        &A[(size_t)(m0 + r) * KTOT + kt * BK + c]);
                else
                    aU[i] = make_uint4(0, 0, 0, 0);
            }
        } else {
            const float* A = (const float*)Ap;
#pragma unroll
            for (int i = 0; i < 4; i++) {
                int idx = tid + i * 256;
                int r = idx >> 3;
                int c = (idx & 7) * 4;
                float4 v = make_float4(0.f, 0.f, 0.f, 0.f);
                if (m0 + r < M)
                    v = *reinterpret_cast<const float4*>(
                        &A[(size_t)(m0 + r) * KTOT + kt * BK + c]);
                aH[i].x = packh2(v.x, v.y);
                aH[i].y = packh2(v.z, v.w);
            }
        }
    };

    auto storeA = [&](int buf) {
        __half* dst = Ash + buf * BM * PA;
        if (AHALF) {
#pragma unroll
            for (int i = 0; i < 2; i++) {
                int idx = tid + i * 256;
                int r = idx >> 2;
                int c = (idx & 3) * 8;
                *reinterpret_cast<uint4*>(&dst[r * PA + c]) = aU[i];
            }
        } else {
#pragma unroll
            for (int i = 0; i < 4; i++) {
                int idx = tid + i * 256;
                int r = idx >> 3;
                int c = (idx & 7) * 4;
                *reinterpret_cast<uint2*>(&dst[r * PA + c]) = aH[i];
            }
        }
    };

    // prologue: load FULL B into smem (fp32 -> fp16)
    {
        const int NB4 = KTOT * BN / 4;
#pragma unroll 4
        for (int idx = tid; idx < NB4; idx += 256) {
            int r = idx / (BN / 4);
            int c = (idx % (BN / 4)) * 4;
            float4 v = *reinterpret_cast<const float4*>(&B[(size_t)r * BN + c]);
            uint2 u;
            u.x = packh2(v.x, v.y);
            u.y = packh2(v.z, v.w);
            *reinterpret_cast<uint2*>(&Bsh[r * PB + c]) = u;
        }
    }
    loadA(0);
    storeA(0);
    __syncthreads();

    uint32_t aBase = (uint32_t)__cvta_generic_to_shared(Ash);
    uint32_t bBase = (uint32_t)__cvta_generic_to_shared(Bsh);

    for (int kt = 0; kt < NKT; kt++) {
        if (kt + 1 < NKT) loadA(kt + 1);
        int cur = kt & 1;
        uint32_t aB = aBase + cur * ABYTES;
#pragma unroll
        for (int ks = 0; ks < 2; ks++) {
            uint4 af[4];
#pragma unroll
            for (int mi = 0; mi < 4; mi++) {
                int row = wm * 64 + mi * 16 + l7 + l8 * 8;
                int col = ks * 16 + l16 * 8;
                af[mi] = ldsm_x4(aB + (row * PA + col) * 2);
            }
            uint4 bf[NPAIR];
#pragma unroll
            for (int p = 0; p < NPAIR; p++) {
                int k = kt * BK + ks * 16 + l7 + l8 * 8;
                int n = wn * (BN / 4) + p * 16 + l16 * 8;
                bf[p] = ldsm_x4_trans(bBase + (k * PB + n) * 2);
            }
#pragma unroll
            for (int mi = 0; mi < 4; mi++)
#pragma unroll
                for (int p = 0; p < NPAIR; p++) {
                    mma_f16(acc[mi][2 * p], af[mi], bf[p].x, bf[p].y);
                    mma_f16(acc[mi][2 * p + 1], af[mi], bf[p].z, bf[p].w);
                }
        }
        if (kt + 1 < NKT) storeA(cur ^ 1);
        __syncthreads();
    }

    const int tig = lane & 3;
    const int grp = lane >> 2;
#pragma unroll
    for (int mi = 0; mi < 4; mi++) {
#pragma unroll
        for (int ni = 0; ni < TN_AT; ni++) {
            int row = m0 + wm * 64 + mi * 16 + grp;
            int col = wn * (BN / 4) + ni * 8 + tig * 2;
            if (row < M)
                *reinterpret_cast<uint32_t*>(&C[(size_t)row * BN + col]) =
                    packh2(acc[mi][ni][0], acc[mi][ni][1]);
            if (row + 8 < M)
                *reinterpret_cast<uint32_t*>(&C[(size_t)(row + 8) * BN + col]) =
                    packh2(acc[mi][ni][2], acc[mi][ni][3]);
        }
    }
}

// ---------------- gather: SUB-WARP per node, packed CSR -------------------
__device__ __forceinline__ void unpack8(uint4 u, float* f) {
    float2 p0 = __half22float2(*reinterpret_cast<__half2*>(&u.x));
    float2 p1 = __half22float2(*reinterpret_cast<__half2*>(&u.y));
    float2 p2 = __half22float2(*reinterpret_cast<__half2*>(&u.z));
    float2 p3 = __half22float2(*reinterpret_cast<__half2*>(&u.w));
    f[0] = p0.x; f[1] = p0.y; f[2] = p1.x; f[3] = p1.y;
    f[4] = p2.x; f[5] = p2.y; f[6] = p3.x; f[7] = p3.y;
}

template <int F, int FUSE>
__global__ void __launch_bounds__(256)
gather_relu_kernel(const __half* __restrict__ xw, const float* __restrict__ bias,
                   __half* __restrict__ out, const int* __restrict__ batch) {
    const int SUBW = F / 8;
    const int NPB = 256 / SUBW;
    __shared__ float spool[FUSE ? NGRAPH * NCLASS : 1];
    __shared__ int sb0, sb1;

    int lane = threadIdx.x & 31;
    int sub = lane / SUBW;
    int li = lane % SUBW;
    int warpId = (blockIdx.x * blockDim.x + threadIdx.x) >> 5;
    int node = warpId * (32 / SUBW) + sub;

    if (FUSE) {
        int n0 = blockIdx.x * NPB;
        if (threadIdx.x == 0) {
            sb0 = load_idx(batch, n0);
            int nl = n0 + NPB - 1;
            sb1 = load_idx(batch, nl < NN ? nl : NN - 1);
        }
        __syncthreads();
        for (int idx = threadIdx.x; idx < (sb1 - sb0 + 1) * NCLASS; idx += 256)
            spool[sb0 * NCLASS + idx] = 0.f;
        __syncthreads();
    }

    const unsigned mask = (((1u << (SUBW - 1)) << 1) - 1u) << (sub * SUBW);
    float acc[8];
    int g = 0;
    if (node < NN) {
        float dn = d_dinv[node];
        int cnt = d_counts[node];
        int rs = d_rowstart[node] - cnt;   // rowstart holds END after csr_fill
        if (FUSE && li == 0) {             // last consumer: reset for next call
            d_counts[node] = 0;
            d_deg[node] = 0.f;
        }
        {
            uint4 u = *reinterpret_cast<const uint4*>(xw + (size_t)node * F + li * 8);
            float v[8];
            unpack8(u, v);
            float dn2 = dn * dn;
#pragma unroll
            for (int q = 0; q < 8; q++) acc[q] = v[q] * dn2;
        }
        for (int base = 0; base < cnt; base += SUBW) {
            int rem = cnt - base;
            if (rem > SUBW) rem = SUBW;
            int sl = 0;
            float vl = 0.f;
            if (li < rem) {
                int2 sv = d_csr[rs + base + li];
                sl = sv.x;
                vl = __int_as_float(sv.y) * dn;
            }
#pragma unroll 8
            for (int j = 0; j < rem; j++) {
                int   sj = __shfl_sync(mask, sl, j, SUBW);
                float vj = __shfl_sync(mask, vl, j, SUBW);
                uint4 u = *reinterpret_cast<const uint4*>(xw + (size_t)sj * F + li * 8);
                float v[8];
                unpack8(u, v);
#pragma unroll
                for (int q = 0; q < 8; q++) acc[q] = fmaf(v[q], vj, acc[q]);
            }
        }
        if (FUSE) g = load_idx(batch, node);
    }

    if (FUSE) {
        if (node < NN) {
            const float* bp = bias + li * 8;
            float* pp = &spool[g * NCLASS + li * 8];
#pragma unroll
            for (int q = 0; q < 8; q++)
                atomicAdd(&pp[q], fmaxf(acc[q] + bp[q], 0.f));
        }
        __syncthreads();
        for (int idx = threadIdx.x; idx < (sb1 - sb0 + 1) * NCLASS; idx += 256)
            atomicAdd(&d_pooled[sb0 * NCLASS + idx], spool[sb0 * NCLASS + idx]);
    } else if (node < NN) {
        const float* bp = bias + li * 8;
        uint4 o;
        o.x = packh2(fmaxf(acc[0] + bp[0], 0.f), fmaxf(acc[1] + bp[1], 0.f));
        o.y = packh2(fmaxf(acc[2] + bp[2], 0.f), fmaxf(acc[3] + bp[3], 0.f));
        o.z = packh2(fmaxf(acc[4] + bp[4], 0.f), fmaxf(acc[5] + bp[5], 0.f));
        o.w = packh2(fmaxf(acc[6] + bp[6], 0.f), fmaxf(acc[7] + bp[7], 0.f));
        *reinterpret_cast<uint4*>(out + (size_t)node * F + li * 8) = o;
    }
}

// ---------------- tiny MLP head + log_softmax + argmax ----------------
__global__ void head_kernel(const float* __restrict__ l1w, const float* __restrict__ l1b,
                            const float* __restrict__ l2w, const float* __restrict__ l2b,
                            float* __restrict__ out) {
    int g = threadIdx.x;
    if (g >= NGRAPH) return;
    float h[64];
#pragma unroll 4
    for (int j = 0; j < 64; j++) {
        float acc = l1b[j];
        for (int k = 0; k < 64; k++)
            acc = fmaf(d_pooled[g * 64 + k], l1w[k * 64 + j], acc);
        h[j] = fmaxf(acc, 0.f);
    }
    float o0 = l2b[0], o1 = l2b[1];
    for (int k = 0; k < 64; k++) {
        o0 = fmaf(h[k], l2w[k * 2 + 0], o0);
        o1 = fmaf(h[k], l2w[k * 2 + 1], o1);
    }
    float m = fmaxf(o0, o1);
    float lse = m + logf(expf(o0 - m) + expf(o1 - m));
    out[g * 2 + 0] = o0 - lse;
    out[g * 2 + 1] = o1 - lse;
    out[128 + g] = (o1 > o0) ? 1.0f : 0.0f;
    out[192 + g * 2 + 0] = o0;
    out[192 + g * 2 + 1] = o1;
}

// ---------------- launch ----------------
extern "C" void kernel_launch(void* const* d_in, const int* in_sizes, int n_in,
                              void* d_out, int out_size) {
    const float* x     = (const float*)d_in[0];
    const int*   ei    = (const int*)d_in[1];
    const float* ew    = (const float*)d_in[2];
    const int*   batch = (const int*)d_in[3];
    const float* W1 = (const float*)d_in[4];
    const float* b1 = (const float*)d_in[5];
    const float* W2 = (const float*)d_in[6];
    const float* b2 = (const float*)d_in[7];
    const float* l1w = (const float*)d_in[8];
    const float* l1b = (const float*)d_in[9];
    const float* l2w = (const float*)d_in[10];
    const float* l2b = (const float*)d_in[11];
    float* out = (float*)d_out;

    __half* xw1; cudaGetSymbolAddress((void**)&xw1, d_xw1);
    __half* h1;  cudaGetSymbolAddress((void**)&h1, d_h1);
    __half* xw2; cudaGetSymbolAddress((void**)&xw2, d_xw2);

    const int NB = (NN + 1023) / 1024;        // 98
    const int MB = (NN + 127) / 128;          // 782
    const int EB4 = (NE / 4 + 255) / 256;     // 1563
    const int GW1 = (NN + 15) / 16;           // 6250
    const int GW2 = (NN + 31) / 32;           // 3125

    // dynamic smem: A double buffer + full B
    constexpr int SM1 = (2 * 128 * 40 + NFEAT * (NHID1 + 8)) * 2;  // 90112 B
    constexpr int SM2 = (2 * 128 * 40 + NHID1 * (NCLASS + 8)) * 2; // 38912 B
    cudaFuncSetAttribute(hgemm_kernel<NHID1, NFEAT, 0>,
                         cudaFuncAttributeMaxDynamicSharedMemorySize, SM1);
    cudaFuncSetAttribute(hgemm_kernel<NCLASS, NHID1, 1>,
                         cudaFuncAttributeMaxDynamicSharedMemorySize, SM2);

    detect_kernel<<<1, 32>>>(ei);                                        // 1
    edge_deg_kernel<<<EB4, 256>>>(ei, ew);                               // 2
    scan_dinv_kernel<<<NB, 1024>>>();                                    // 3
    hgemm_kernel<NHID1, NFEAT, 0><<<MB, 256, SM1>>>(x, W1, xw1, NN);     // 4 <- ncu
    add_offsets_kernel<<<NB, 1024>>>(NB);                                // 5
    csr_fill_kernel<<<EB4, 256>>>(ei, ew);                               // 6
    gather_relu_kernel<NHID1, 0><<<GW1, 256>>>(xw1, b1, h1, batch);      // 7
    hgemm_kernel<NCLASS, NHID1, 1><<<MB, 256, SM2>>>(h1, W2, xw2, NN);   // 8
    gather_relu_kernel<NCLASS, 1><<<GW2, 256>>>(xw2, b2, nullptr, batch);// 9
    head_kernel<<<1, 64>>>(l1w, l1b, l2w, l2b, out);                     // 10
}

// round 14
// speedup vs baseline: 1.0688x; 1.0688x over previous
#include <cuda_runtime.h>
#include <cuda_fp16.h>
#include <math.h>
#include <stdint.h>

#define NN 100000
#define NE 1600000
#define NFEAT 256
#define NHID1 128
#define NCLASS 64
#define NGRAPH 64

// ---------------- scratch (device globals; no allocation) ----------------
__device__ int    d_idx64;
__device__ float  d_deg[NN];
__device__ float  d_dinv[NN];
__device__ int    d_counts[NN];
__device__ int    d_rowstart[NN];
__device__ int    d_cursor[NN];
__device__ int    d_blockSums[128];
__device__ int2   d_csr[NE];          // (src, val-bits) packed
__device__ __half d_xw1[NN * NHID1];
__device__ __half d_h1[NN * NHID1];
__device__ __half d_xw2[NN * NCLASS];
__device__ float  d_pooled[NGRAPH * NCLASS];

__device__ __forceinline__ int load_idx(const int* __restrict__ p, long long i) {
    return d_idx64 ? p[2 * i] : p[i];
}

// ---------------- init + dtype detect ----------------
__global__ void init_detect_kernel(const int* __restrict__ ei) {
    int i = blockIdx.x * blockDim.x + threadIdx.x;
    if (i < NN) { d_deg[i] = 1.0f; d_counts[i] = 0; }
    if (i == 0) {
        int allzero = 1;
        for (int k = 0; k < 128; k++)
            if (ei[2 * k + 1] != 0) { allzero = 0; break; }
        d_idx64 = allzero;
    }
}

// ---------------- degree accumulation (4 edges / thread) ----------------
__global__ void edge_deg_kernel(const int* __restrict__ ei,
                                const float* __restrict__ ew) {
    int e = (blockIdx.x * blockDim.x + threadIdx.x) * 4;
    if (e >= NE) return;
    int c[4];
    if (d_idx64) {
        const int4* p = reinterpret_cast<const int4*>(ei + 2LL * (NE + e));
        int4 a = p[0], b = p[1];
        c[0] = a.x; c[1] = a.z; c[2] = b.x; c[3] = b.z;
    } else {
        int4 a = *reinterpret_cast<const int4*>(ei + NE + e);
        c[0] = a.x; c[1] = a.y; c[2] = a.z; c[3] = a.w;
    }
    float4 w = *reinterpret_cast<const float4*>(ew + e);
    float wv[4] = {w.x, w.y, w.z, w.w};
#pragma unroll
    for (int j = 0; j < 4; j++) {
        atomicAdd(&d_deg[c[j]], wv[j]);
        atomicAdd(&d_counts[c[j]], 1);
    }
}

// ---------------- block scan of counts + dinv ----------------
__global__ void scan_dinv_kernel() {
    __shared__ int s[1024];
    int i = blockIdx.x * 1024 + threadIdx.x;
    int v = (i < NN) ? d_counts[i] : 0;
    s[threadIdx.x] = v;
    if (i < NN) d_dinv[i] = rsqrtf(d_deg[i]);
    __syncthreads();
    for (int off = 1; off < 1024; off <<= 1) {
        int t = (threadIdx.x >= off) ? s[threadIdx.x - off] : 0;
        __syncthreads();
        s[threadIdx.x] += t;
        __syncthreads();
    }
    if (i < NN) d_rowstart[i] = s[threadIdx.x] - v;
    if (threadIdx.x == 1023) d_blockSums[blockIdx.x] = s[1023];
}

// ---------------- per-block prefix + offsets + pool zeroing ----------------
__global__ void add_offsets_kernel(int nb) {
    __shared__ int total;
    if (threadIdx.x == 0) total = 0;
    __syncthreads();
    if (threadIdx.x < (unsigned)blockIdx.x && threadIdx.x < (unsigned)nb)
        atomicAdd(&total, d_blockSums[threadIdx.x]);
    __syncthreads();
    int i = blockIdx.x * 1024 + threadIdx.x;
    if (i < NN) {
        int v = d_rowstart[i] + total;
        d_rowstart[i] = v;
        d_cursor[i]  = v;
    }
    if (i < NGRAPH * NCLASS) d_pooled[i] = 0.f;
}

// ---------------- CSR fill (4 edges / thread, packed int2 store) ----------
__global__ void csr_fill_kernel(const int* __restrict__ ei,
                                const float* __restrict__ ew) {
    int e = (blockIdx.x * blockDim.x + threadIdx.x) * 4;
    if (e >= NE) return;
    int r[4], c[4];
    if (d_idx64) {
        const int4* pr = reinterpret_cast<const int4*>(ei + 2LL * e);
        int4 a = pr[0], b = pr[1];
        r[0] = a.x; r[1] = a.z; r[2] = b.x; r[3] = b.z;
        const int4* pc = reinterpret_cast<const int4*>(ei + 2LL * (NE + e));
        int4 d = pc[0], f = pc[1];
        c[0] = d.x; c[1] = d.z; c[2] = f.x; c[3] = f.z;
    } else {
        int4 a = *reinterpret_cast<const int4*>(ei + e);
        r[0] = a.x; r[1] = a.y; r[2] = a.z; r[3] = a.w;
        int4 d = *reinterpret_cast<const int4*>(ei + NE + e);
        c[0] = d.x; c[1] = d.y; c[2] = d.z; c[3] = d.w;
    }
    float4 w = *reinterpret_cast<const float4*>(ew + e);
    float wv[4] = {w.x, w.y, w.z, w.w};
#pragma unroll
    for (int j = 0; j < 4; j++) {
        int pos = atomicAdd(&d_cursor[c[j]], 1);
        d_csr[pos] = make_int2(r[j], __float_as_int(d_dinv[r[j]] * wv[j]));
    }
}

// ---------------- fp16 tensor-core GEMM (R7/R11 config, verified 45us) -----
__device__ __forceinline__ uint32_t packh2(float a, float b) {
    __half2 h = __floats2half2_rn(a, b);
    return *reinterpret_cast<uint32_t*>(&h);
}

__device__ __forceinline__ uint4 ldsm_x4(uint32_t addr) {
    uint4 r;
    asm volatile("ldmatrix.sync.aligned.m8n8.x4.shared.b16 {%0,%1,%2,%3}, [%4];"
                 : "=r"(r.x), "=r"(r.y), "=r"(r.z), "=r"(r.w) : "r"(addr));
    return r;
}

__device__ __forceinline__ uint4 ldsm_x4_trans(uint32_t addr) {
    uint4 r;
    asm volatile("ldmatrix.sync.aligned.m8n8.x4.trans.shared.b16 {%0,%1,%2,%3}, [%4];"
                 : "=r"(r.x), "=r"(r.y), "=r"(r.z), "=r"(r.w) : "r"(addr));
    return r;
}

__device__ __forceinline__ void mma_f16(float* c, uint4 a, uint32_t b0, uint32_t b1) {
    asm volatile(
        "mma.sync.aligned.m16n8k16.row.col.f32.f16.f16.f32 "
        "{%0,%1,%2,%3},{%4,%5,%6,%7},{%8,%9},{%0,%1,%2,%3};\n"
        : "+f"(c[0]), "+f"(c[1]), "+f"(c[2]), "+f"(c[3])
        : "r"(a.x), "r"(a.y), "r"(a.z), "r"(a.w), "r"(b0), "r"(b1));
}

template <int BN, int AHALF>
__global__ void __launch_bounds__(256, 2)
hgemm_kernel(const void* __restrict__ Ap, const float* __restrict__ B,
             __half* __restrict__ C, int M, int K) {
    const int BM = 128, BK = 32;
    const int PA = 40;
    const int PB = BN + 8;
    const int TN_AT = BN / 32;
    const int NPAIR = BN / 64;
    const int ABYTES = BM * PA * 2;
    const int BBYTES = BK * PB * 2;

    __shared__ __half Ash[2][BM * PA];
    __shared__ __half Bsh[2][BK * PB];

    const int tid = threadIdx.x;
    const int lane = tid & 31;
    const int warp = tid >> 5;
    const int wm = warp & 1;
    const int wn = warp >> 1;
    const int m0 = blockIdx.x * BM;
    const int nk = K / BK;

    const int l7 = lane & 7;
    const int l8 = (lane >> 3) & 1;
    const int l16 = lane >> 4;

    float acc[4][TN_AT][4];
#pragma unroll
    for (int i = 0; i < 4; i++)
#pragma unroll
        for (int j = 0; j < TN_AT; j++)
#pragma unroll
            for (int q = 0; q < 4; q++) acc[i][j][q] = 0.f;

    uint4 aU[2];
    uint2 aH[4];
    uint2 bH[BN / 32];

    auto loadG = [&](int kt) {
        if (AHALF) {
            const __half* A = (const __half*)Ap;
#pragma unroll
            for (int i = 0; i < 2; i++) {
                int idx = tid + i * 256;
                int r = idx >> 2;
                int c = (idx & 3) * 8;
                if (m0 + r < M)
                    aU[i] = *reinterpret_cast<const uint4*>(
                        &A[(size_t)(m0 + r) * K + kt * BK + c]);
                else
                    aU[i] = make_uint4(0, 0, 0, 0);
            }
        } else {
            const float* A = (const float*)Ap;
#pragma unroll
            for (int i = 0; i < 4; i++) {
                int idx = tid + i * 256;
                int r = idx >> 3;
                int c = (idx & 7) * 4;
                float4 v = make_float4(0.f, 0.f, 0.f, 0.f);
                if (m0 + r < M)
                    v = *reinterpret_cast<const float4*>(
                        &A[(size_t)(m0 + r) * K + kt * BK + c]);
                aH[i].x = packh2(v.x, v.y);
                aH[i].y = packh2(v.z, v.w);
            }
        }
#pragma unroll
        for (int i = 0; i < BN / 32; i++) {
            int idx = tid + i * 256;
            int r = idx / (BN / 4);
            int c = (idx % (BN / 4)) * 4;
            float4 v = *reinterpret_cast<const float4*>(
                &B[(size_t)(kt * BK + r) * BN + c]);
            bH[i].x = packh2(v.x, v.y);
            bH[i].y = packh2(v.z, v.w);
        }
    };

    auto storeS = [&](int buf) {
        if (AHALF) {
#pragma unroll
            for (int i = 0; i < 2; i++) {
                int idx = tid + i * 256;
                int r = idx >> 2;
                int c = (idx & 3) * 8;
                *reinterpret_cast<uint4*>(&Ash[buf][r * PA + c]) = aU[i];
            }
        } else {
#pragma unroll
            for (int i = 0; i < 4; i++) {
                int idx = tid + i * 256;
                int r = idx >> 3;
                int c = (idx & 7) * 4;
                *reinterpret_cast<uint2*>(&Ash[buf][r * PA + c]) = aH[i];
            }
        }
#pragma unroll
        for (int i = 0; i < BN / 32; i++) {
            int idx = tid + i * 256;
            int r = idx / (BN / 4);
            int c = (idx % (BN / 4)) * 4;
            *reinterpret_cast<uint2*>(&Bsh[buf][r * PB + c]) = bH[i];
        }
    };

    uint32_t aBase = (uint32_t)__cvta_generic_to_shared(&Ash[0][0]);
    uint32_t bBase = (uint32_t)__cvta_generic_to_shared(&Bsh[0][0]);

    loadG(0);
    storeS(0);
    __syncthreads();

    for (int kt = 0; kt < nk; kt++) {
        if (kt + 1 < nk) loadG(kt + 1);
        int cur = kt & 1;
        uint32_t aB = aBase + cur * ABYTES;
        uint32_t bB = bBase + cur * BBYTES;
#pragma unroll
        for (int ks = 0; ks < 2; ks++) {
            uint4 af[4];
#pragma unroll
            for (int mi = 0; mi < 4; mi++) {
                int row = wm * 64 + mi * 16 + l7 + l8 * 8;
                int col = ks * 16 + l16 * 8;
                af[mi] = ldsm_x4(aB + (row * PA + col) * 2);
            }
            uint4 bf[NPAIR];
#pragma unroll
            for (int p = 0; p < NPAIR; p++) {
                int k = ks * 16 + l7 + l8 * 8;
                int n = wn * (BN / 4) + p * 16 + l16 * 8;
                bf[p] = ldsm_x4_trans(bB + (k * PB + n) * 2);
            }
#pragma unroll
            for (int mi = 0; mi < 4; mi++)
#pragma unroll
                for (int p = 0; p < NPAIR; p++) {
                    mma_f16(acc[mi][2 * p], af[mi], bf[p].x, bf[p].y);
                    mma_f16(acc[mi][2 * p + 1], af[mi], bf[p].z, bf[p].w);
                }
        }
        if (kt + 1 < nk) storeS(cur ^ 1);
        __syncthreads();
    }

    const int tig = lane & 3;
    const int grp = lane >> 2;
#pragma unroll
    for (int mi = 0; mi < 4; mi++) {
#pragma unroll
        for (int ni = 0; ni < TN_AT; ni++) {
            int row = m0 + wm * 64 + mi * 16 + grp;
            int col = wn * (BN / 4) + ni * 8 + tig * 2;
            if (row < M)
                *reinterpret_cast<uint32_t*>(&C[(size_t)row * BN + col]) =
                    packh2(acc[mi][ni][0], acc[mi][ni][1]);
            if (row + 8 < M)
                *reinterpret_cast<uint32_t*>(&C[(size_t)(row + 8) * BN + col]) =
                    packh2(acc[mi][ni][2], acc[mi][ni][3]);
        }
    }
}

// ---------------- gather: SUB-WARP per node, packed CSR -------------------
__device__ __forceinline__ void unpack8(uint4 u, float* f) {
    float2 p0 = __half22float2(*reinterpret_cast<__half2*>(&u.x));
    float2 p1 = __half22float2(*reinterpret_cast<__half2*>(&u.y));
    float2 p2 = __half22float2(*reinterpret_cast<__half2*>(&u.z));
    float2 p3 = __half22float2(*reinterpret_cast<__half2*>(&u.w));
    f[0] = p0.x; f[1] = p0.y; f[2] = p1.x; f[3] = p1.y;
    f[4] = p2.x; f[5] = p2.y; f[6] = p3.x; f[7] = p3.y;
}

template <int F, int FUSE>
__global__ void __launch_bounds__(256)
gather_relu_kernel(const __half* __restrict__ xw, const float* __restrict__ bias,
                   __half* __restrict__ out, const int* __restrict__ batch) {
    const int SUBW = F / 8;
    const int NPB = 256 / SUBW;
    __shared__ float spool[FUSE ? NGRAPH * NCLASS : 1];
    __shared__ int sb0, sb1;

    int lane = threadIdx.x & 31;
    int sub = lane / SUBW;
    int li = lane % SUBW;
    int warpId = (blockIdx.x * blockDim.x + threadIdx.x) >> 5;
    int node = warpId * (32 / SUBW) + sub;

    if (FUSE) {
        int n0 = blockIdx.x * NPB;
        if (threadIdx.x == 0) {
            sb0 = load_idx(batch, n0);
            int nl = n0 + NPB - 1;
            sb1 = load_idx(batch, nl < NN ? nl : NN - 1);
        }
        __syncthreads();
        for (int idx = threadIdx.x; idx < (sb1 - sb0 + 1) * NCLASS; idx += 256)
            spool[sb0 * NCLASS + idx] = 0.f;
        __syncthreads();
    }

    const unsigned mask = (((1u << (SUBW - 1)) << 1) - 1u) << (sub * SUBW);
    float acc[8];
    int g = 0;
    if (node < NN) {
        float dn = d_dinv[node];
        int rs = d_rowstart[node];
        int cnt = d_counts[node];
        {
            uint4 u = *reinterpret_cast<const uint4*>(xw + (size_t)node * F + li * 8);
            float v[8];
            unpack8(u, v);
            float dn2 = dn * dn;
#pragma unroll
            for (int q = 0; q < 8; q++) acc[q] = v[q] * dn2;
        }
        for (int base = 0; base < cnt; base += SUBW) {
            int rem = cnt - base;
            if (rem > SUBW) rem = SUBW;
            int sl = 0;
            float vl = 0.f;
            if (li < rem) {
                int2 sv = d_csr[rs + base + li];
                sl = sv.x;
                vl = __int_as_float(sv.y) * dn;
            }
#pragma unroll 8
            for (int j = 0; j < rem; j++) {
                int   sj = __shfl_sync(mask, sl, j, SUBW);
                float vj = __shfl_sync(mask, vl, j, SUBW);
                uint4 u = *reinterpret_cast<const uint4*>(xw + (size_t)sj * F + li * 8);
                float v[8];
                unpack8(u, v);
#pragma unroll
                for (int q = 0; q < 8; q++) acc[q] = fmaf(v[q], vj, acc[q]);
            }
        }
        if (FUSE) g = load_idx(batch, node);
    }

    if (FUSE) {
        if (node < NN) {
            const float* bp = bias + li * 8;
            float* pp = &spool[g * NCLASS + li * 8];
#pragma unroll
            for (int q = 0; q < 8; q++)
                atomicAdd(&pp[q], fmaxf(acc[q] + bp[q], 0.f));
        }
        __syncthreads();
        for (int idx = threadIdx.x; idx < (sb1 - sb0 + 1) * NCLASS; idx += 256)
            atomicAdd(&d_pooled[sb0 * NCLASS + idx], spool[sb0 * NCLASS + idx]);
    } else if (node < NN) {
        const float* bp = bias + li * 8;
        uint4 o;
        o.x = packh2(fmaxf(acc[0] + bp[0], 0.f), fmaxf(acc[1] + bp[1], 0.f));
        o.y = packh2(fmaxf(acc[2] + bp[2], 0.f), fmaxf(acc[3] + bp[3], 0.f));
        o.z = packh2(fmaxf(acc[4] + bp[4], 0.f), fmaxf(acc[5] + bp[5], 0.f));
        o.w = packh2(fmaxf(acc[6] + bp[6], 0.f), fmaxf(acc[7] + bp[7], 0.f));
        *reinterpret_cast<uint4*>(out + (size_t)node * F + li * 8) = o;
    }
}

// ---------------- tiny MLP head + log_softmax + argmax ----------------
__global__ void head_kernel(const float* __restrict__ l1w, const float* __restrict__ l1b,
                            const float* __restrict__ l2w, const float* __restrict__ l2b,
                            float* __restrict__ out) {
    int g = threadIdx.x;
    if (g >= NGRAPH) return;
    float h[64];
#pragma unroll 4
    for (int j = 0; j < 64; j++) {
        float acc = l1b[j];
        for (int k = 0; k < 64; k++)
            acc = fmaf(d_pooled[g * 64 + k], l1w[k * 64 + j], acc);
        h[j] = fmaxf(acc, 0.f);
    }
    float o0 = l2b[0], o1 = l2b[1];
    for (int k = 0; k < 64; k++) {
        o0 = fmaf(h[k], l2w[k * 2 + 0], o0);
        o1 = fmaf(h[k], l2w[k * 2 + 1], o1);
    }
    float m = fmaxf(o0, o1);
    float lse = m + logf(expf(o0 - m) + expf(o1 - m));
    out[g * 2 + 0] = o0 - lse;
    out[g * 2 + 1] = o1 - lse;
    out[128 + g] = (o1 > o0) ? 1.0f : 0.0f;
    out[192 + g * 2 + 0] = o0;
    out[192 + g * 2 + 1] = o1;
}

// ---------------- launch (stream fork/join: GEMM1 || CSR prep) -------------
extern "C" void kernel_launch(void* const* d_in, const int* in_sizes, int n_in,
                              void* d_out, int out_size) {
    const float* x     = (const float*)d_in[0];
    const int*   ei    = (const int*)d_in[1];
    const float* ew    = (const float*)d_in[2];
    const int*   batch = (const int*)d_in[3];
    const float* W1 = (const float*)d_in[4];
    const float* b1 = (const float*)d_in[5];
    const float* W2 = (const float*)d_in[6];
    const float* b2 = (const float*)d_in[7];
    const float* l1w = (const float*)d_in[8];
    const float* l1b = (const float*)d_in[9];
    const float* l2w = (const float*)d_in[10];
    const float* l2b = (const float*)d_in[11];
    float* out = (float*)d_out;

    __half* xw1; cudaGetSymbolAddress((void**)&xw1, d_xw1);
    __half* h1;  cudaGetSymbolAddress((void**)&h1, d_h1);
    __half* xw2; cudaGetSymbolAddress((void**)&xw2, d_xw2);

    // lazy one-time stream/event setup (no device memory; first call is
    // the uncaptured correctness run, so creation never happens mid-capture)
    static cudaStream_t s2 = nullptr;
    static cudaEvent_t evFork = nullptr, evJoin = nullptr;
    if (s2 == nullptr) {
        cudaStreamCreateWithFlags(&s2, cudaStreamNonBlocking);
        cudaEventCreateWithFlags(&evFork, cudaEventDisableTiming);
        cudaEventCreateWithFlags(&evJoin, cudaEventDisableTiming);
    }

    const int NB = (NN + 1023) / 1024;        // 98
    const int MB = (NN + 127) / 128;          // 782
    const int EB4 = (NE / 4 + 255) / 256;     // 1563
    const int GW1 = (NN + 15) / 16;           // 6250
    const int GW2 = (NN + 31) / 32;           // 3125

    // fork: GEMM1 (independent of graph prep) runs on s2
    cudaEventRecord(evFork, 0);
    cudaStreamWaitEvent(s2, evFork, 0);
    hgemm_kernel<NHID1, 0><<<MB, 256, 0, s2>>>(x, W1, xw1, NN, NFEAT);

    // CSR prep chain on default stream
    init_detect_kernel<<<(NN + 255) / 256, 256>>>(ei);
    edge_deg_kernel<<<EB4, 256>>>(ei, ew);
    scan_dinv_kernel<<<NB, 1024>>>();
    add_offsets_kernel<<<NB, 1024>>>(NB);
    csr_fill_kernel<<<EB4, 256>>>(ei, ew);

    // join: gather1 needs xw1 (s2) + csr (default)
    cudaEventRecord(evJoin, s2);
    cudaStreamWaitEvent(0, evJoin, 0);

    gather_relu_kernel<NHID1, 0><<<GW1, 256>>>(xw1, b1, h1, batch);
    hgemm_kernel<NCLASS, 1><<<MB, 256>>>(h1, W2, xw2, NN, NHID1);
    gather_relu_kernel<NCLASS, 1><<<GW2, 256>>>(xw2, b2, nullptr, batch);
    head_kernel<<<1, 64>>>(l1w, l1b, l2w, l2b, out);
}